// round 5
// baseline (speedup 1.0000x reference)
#include <cuda_runtime.h>
#include <math.h>

// ---------------- problem constants ----------------
#define R_CNT   1000000
#define NGEO    1024
#define BB      64
#define LD      65            // padded row stride (bank-conflict-free columns)
#define NEL     7
#define EREPN   2000000
#define NNET    4000000
#define ROT_LEN (2 + R_CNT*9)
#define NSWEEP_MAX 30

// ---------------- output layout (flattened tuple) ----------------
#define OFF_H     0
#define OFF_DQ    (NGEO*BB*BB)               // 4194304
#define OFF_EREP  (OFF_DQ + NGEO*BB)         // 4259840
#define OFF_EORB  (OFF_EREP + NGEO)          // 4260864
#define OFF_RHO   (OFF_EORB + NGEO*BB)       // 4326400
#define OFF_EELEC (OFF_RHO + NGEO*BB*BB)     // 8520704
#define OFF_EREF  (OFF_EELEC + NGEO)         // 8521728

// scratch: rotated sp-block table (36 MB)
__device__ float g_rot_out[ROT_LEN];

// ---------------- stage 1: rotation (SMEM-staged coalesced T reads) ----------------
__global__ void __launch_bounds__(256) k_rot(
    const float* __restrict__ net,
    const float* __restrict__ T,
    const int*   __restrict__ gidx)
{
    __shared__ float sT[256 * 27];   // 27 KB staging
    const int tid  = threadIdx.x;
    const int base = blockIdx.x * 256;          // first r of this block
    const int cnt  = min(256, R_CNT - base);    // rows this block owns
    if (cnt <= 0) return;

    // coalesced stage: cnt*27 contiguous floats
    const float* Tb = T + (size_t)base * 27;
    for (int i = tid; i < cnt * 27; i += 256) sT[i] = Tb[i];
    __syncthreads();

    if (tid >= cnt) return;
    const int r = base + tid;
    if (r == 0) { g_rot_out[0] = 0.0f; g_rot_out[1] = 1.0f; }
    float v0 = net[gidx[3*r + 0]];
    float v1 = net[gidx[3*r + 1]];
    float v2 = net[gidx[3*r + 2]];
    const float* t = sT + tid * 27;   // stride 27 vs 32 banks: conflict-free
    float* o = g_rot_out + 2 + (size_t)r * 9;
#pragma unroll
    for (int i = 0; i < 9; i++)
        o[i] = t[3*i + 0] * v0 + t[3*i + 1] * v1 + t[3*i + 2] * v2;
}

// ---------------- stage 2: H gather ----------------
__global__ void k_hgather(const int* __restrict__ gop, float* __restrict__ out)
{
    int i = blockIdx.x * blockDim.x + threadIdx.x;
    if (i < NGEO*BB*BB) out[OFF_H + i] = g_rot_out[gop[i]];
}

// ---------------- misc: zero Erep, compute Eref ----------------
__global__ void k_misc(const float* __restrict__ zc,
                       const float* __restrict__ rv,
                       float* __restrict__ out)
{
    int i = blockIdx.x * blockDim.x + threadIdx.x;
    if (i < NGEO) out[OFF_EREP + i] = 0.0f;
    if (i == 0) {
        float s = 0.0f;
        for (int e = 0; e < NEL; e++) s += zc[e] * rv[e];
        out[OFF_EREF] = s;
    }
}

// ---------------- stage 3: repulsive segment sum ----------------
__global__ void k_erep(const float* __restrict__ net,
                       const int*   __restrict__ gr,
                       const int*   __restrict__ seg,
                       float* __restrict__ out)
{
    int i = blockIdx.x * blockDim.x + threadIdx.x;
    if (i >= EREPN) return;   // EREPN % 256 == 0 -> whole warps exit uniformly
    int lane = threadIdx.x & 31;
    float v = net[gr[i]];
    int   s = seg[i];
    // inclusive segmented warp scan (segments sorted -> contiguous runs)
#pragma unroll
    for (int off = 1; off < 32; off <<= 1) {
        float nv = __shfl_up_sync(0xffffffffu, v, off);
        int   ns = __shfl_up_sync(0xffffffffu, s, off);
        if (lane >= off && ns == s) v += nv;
    }
    int nxt = __shfl_down_sync(0xffffffffu, s, 1);
    if (lane == 31 || s != nxt)
        atomicAdd(&out[OFF_EREP + s], v);
}

// ---------------- stage 4: per-geometry dense stage ----------------
__global__ void __launch_bounds__(256) k_geom(
    const float* __restrict__ S,   const float* __restrict__ G,
    const float* __restrict__ rho, const float* __restrict__ qn,
    const float* __restrict__ mask,const float* __restrict__ phiS,
    float* __restrict__ out)
{
    extern __shared__ float sm[];
    float* sA = sm;                // working matrix (F -> fockp -> A -> orb)
    float* sB = sm + LD*BB;        // S -> T(=F*P) -> V(eigvecs)
    float* sP = sm + 2*LD*BB;      // phiS
    __shared__ float dq[BB], epv[BB], eig[BB];
    __shared__ float cc[32], ssn[32];
    __shared__ int   ppx[32], qqx[32], perm[BB];
    __shared__ float red[256];
    __shared__ float red2[256];
    __shared__ float s_ener2;
    __shared__ int   s_done;

    const int g = blockIdx.x;
    const int t = threadIdx.x;
    const int w = t >> 5, lane = t & 31;
    const int ty = t >> 4, tx = t & 15;
    const int i0 = ty * 4, j0 = tx * 4;

    const float* Sg = S    + (size_t)g*BB*BB;
    const float* Gg = G    + (size_t)g*BB*BB;
    const float* Rg = rho  + (size_t)g*BB*BB;
    const float* Mg = mask + (size_t)g*BB*BB;
    const float* Pg = phiS + (size_t)g*BB*BB;
    const float* Hg = out + OFF_H + (size_t)g*BB*BB;

    // load S -> sB, phiS -> sP
#pragma unroll
    for (int m = 0; m < 16; m++) {
        int idx = t + m*256; int i = idx >> 6, j = idx & 63;
        sB[i*LD + j] = Sg[idx];
        sP[i*LD + j] = Pg[idx];
    }
    __syncthreads();

    // dQ[i] = qn[i] - sum_j rho[i][j]*S[i][j]
    for (int i = w; i < BB; i += 8) {
        float a = Rg[i*64 + lane]      * sB[i*LD + lane]
                + Rg[i*64 + 32 + lane] * sB[i*LD + 32 + lane];
#pragma unroll
        for (int o = 16; o; o >>= 1) a += __shfl_down_sync(0xffffffffu, a, o);
        if (lane == 0) dq[i] = qn[g*64 + i] - a;
    }
    __syncthreads();

    // ep = G @ dQ
    for (int i = w; i < BB; i += 8) {
        float a = Gg[i*64 + lane]      * dq[lane]
                + Gg[i*64 + 32 + lane] * dq[lane + 32];
#pragma unroll
        for (int o = 16; o; o >>= 1) a += __shfl_down_sync(0xffffffffu, a, o);
        if (lane == 0) epv[i] = a;
    }
    __syncthreads();

    // ener2 = 0.5 * dQ . ep
    if (w == 0) {
        float a = dq[lane]*epv[lane] + dq[lane+32]*epv[lane+32];
#pragma unroll
        for (int o = 16; o; o >>= 1) a += __shfl_down_sync(0xffffffffu, a, o);
        if (lane == 0) s_ener2 = 0.5f * a;
    }
    if (t < 64) out[OFF_DQ + g*64 + t] = dq[t];

    // F = H - 0.5*S*(ep_i + ep_j)  -> sA
#pragma unroll
    for (int m = 0; m < 16; m++) {
        int idx = t + m*256; int i = idx >> 6, j = idx & 63;
        sA[i*LD + j] = Hg[idx] - 0.5f * sB[i*LD + j] * (epv[i] + epv[j]);
    }
    __syncthreads();

    // T = F @ P  -> sB (overwrites S; no one reads S anymore)
    {
        float acc[4][4];
#pragma unroll
        for (int a = 0; a < 4; a++)
#pragma unroll
            for (int b = 0; b < 4; b++) acc[a][b] = 0.0f;
#pragma unroll 4
        for (int k = 0; k < BB; k++) {
            float av[4], bv[4];
#pragma unroll
            for (int a = 0; a < 4; a++) av[a] = sA[(i0+a)*LD + k];
#pragma unroll
            for (int b = 0; b < 4; b++) bv[b] = sP[k*LD + j0 + b];
#pragma unroll
            for (int a = 0; a < 4; a++)
#pragma unroll
                for (int b = 0; b < 4; b++) acc[a][b] += av[a]*bv[b];
        }
        __syncthreads();
#pragma unroll
        for (int a = 0; a < 4; a++)
#pragma unroll
            for (int b = 0; b < 4; b++) sB[(i0+a)*LD + j0 + b] = acc[a][b];
    }
    __syncthreads();

    // fockp = P^T @ T  -> sA
    {
        float acc[4][4];
#pragma unroll
        for (int a = 0; a < 4; a++)
#pragma unroll
            for (int b = 0; b < 4; b++) acc[a][b] = 0.0f;
#pragma unroll 4
        for (int k = 0; k < BB; k++) {
            float av[4], bv[4];
#pragma unroll
            for (int a = 0; a < 4; a++) av[a] = sP[k*LD + i0 + a];
#pragma unroll
            for (int b = 0; b < 4; b++) bv[b] = sB[k*LD + j0 + b];
#pragma unroll
            for (int a = 0; a < 4; a++)
#pragma unroll
                for (int b = 0; b < 4; b++) acc[a][b] += av[a]*bv[b];
        }
        __syncthreads();
#pragma unroll
        for (int a = 0; a < 4; a++)
#pragma unroll
            for (int b = 0; b < 4; b++) sA[(i0+a)*LD + j0 + b] = acc[a][b];
    }
    __syncthreads();

    // V = I  -> sB
#pragma unroll
    for (int m = 0; m < 16; m++) {
        int idx = t + m*256; int i = idx >> 6, j = idx & 63;
        sB[i*LD + j] = (i == j) ? 1.0f : 0.0f;
    }
    if (t == 0) s_done = 0;
    __syncthreads();

    // ----- parallel cyclic Jacobi: A in sA, V in sB -----
    for (int sweep = 0; sweep < NSWEEP_MAX; sweep++) {
        for (int r = 0; r < 63; r++) {
            if (t < 32) {
                int p, q;
                if (t == 0) { p = 63; q = r; }
                else { p = (r + t) % 63; q = (r + 63 - t) % 63; }
                if (p > q) { int tmp = p; p = q; q = tmp; }
                float app = sA[p*LD + p], aqq = sA[q*LD + q];
                float apq = 0.5f * (sA[p*LD + q] + sA[q*LD + p]);  // symmetrized pivot
                float c = 1.0f, s = 0.0f;
                if (fabsf(apq) > 1e-20f) {
                    float tau = (aqq - app) / (2.0f * apq);
                    float tt  = copysignf(1.0f, tau) / (fabsf(tau) + sqrtf(1.0f + tau*tau));
                    c = rsqrtf(1.0f + tt*tt);
                    s = tt * c;
                }
                cc[t] = c; ssn[t] = s; ppx[t] = p; qqx[t] = q;
            }
            __syncthreads();
            // row updates: A <- R^T A
#pragma unroll
            for (int m = 0; m < 8; m++) {
                int u = t + m*256; int k = u >> 6, j = u & 63;
                int p = ppx[k], q = qqx[k];
                float c = cc[k], s = ssn[k];
                float apj = sA[p*LD + j], aqj = sA[q*LD + j];
                sA[p*LD + j] = c*apj - s*aqj;
                sA[q*LD + j] = s*apj + c*aqj;
            }
            __syncthreads();
            // column updates: A <- A R ; V <- V R
#pragma unroll
            for (int m = 0; m < 8; m++) {
                int u = t + m*256; int k = u >> 6, i = u & 63;
                int p = ppx[k], q = qqx[k];
                float c = cc[k], s = ssn[k];
                float aip = sA[i*LD + p], aiq = sA[i*LD + q];
                sA[i*LD + p] = c*aip - s*aiq;
                sA[i*LD + q] = s*aip + c*aiq;
                float vip = sB[i*LD + p], viq = sB[i*LD + q];
                sB[i*LD + p] = c*vip - s*viq;
                sB[i*LD + q] = s*vip + c*viq;
            }
            __syncthreads();
        }
        // ---- convergence check (sum of squares; skip first 4 sweeps) ----
        if (sweep >= 4) {
            float offs = 0.0f, diag = 0.0f;
#pragma unroll
            for (int a = 0; a < 4; a++)
#pragma unroll
                for (int b = 0; b < 4; b++) {
                    int i = i0 + a, j = j0 + b;
                    float v = sA[i*LD + j];
                    if (i == j) diag += v*v; else offs += v*v;
                }
            red[t] = offs;
            red2[t] = diag;
            __syncthreads();
            for (int o = 128; o; o >>= 1) {
                if (t < o) { red[t] += red[t + o]; red2[t] += red2[t + o]; }
                __syncthreads();
            }
            // off_F < 1e-6 * diag_F  (tight: protects eigvecs of near-degenerate pairs)
            if (t == 0 && red[0] < 1e-12f * red2[0]) s_done = 1;
            __syncthreads();
            if (s_done) break;
        }
    }

    // ----- sort eigenvalues ascending (tie-break by index), build perm -----
    if (t < 64) eig[t] = sA[t*LD + t];
    __syncthreads();
    if (t < 64) {
        float v = eig[t];
        int rk = 0;
        for (int j = 0; j < 64; j++) {
            float u = eig[j];
            rk += (u < v) || (u == v && j < t);
        }
        perm[rk] = t;
        out[OFF_EORB + g*64 + rk] = v;
    }
    __syncthreads();

    // orb = P @ V[:, perm], masked -> sA
    {
        int pc[4];
#pragma unroll
        for (int b = 0; b < 4; b++) pc[b] = perm[j0 + b];
        float acc[4][4];
#pragma unroll
        for (int a = 0; a < 4; a++)
#pragma unroll
            for (int b = 0; b < 4; b++) acc[a][b] = 0.0f;
#pragma unroll 4
        for (int k = 0; k < BB; k++) {
            float av[4], bv[4];
#pragma unroll
            for (int a = 0; a < 4; a++) av[a] = sP[(i0+a)*LD + k];
#pragma unroll
            for (int b = 0; b < 4; b++) bv[b] = sB[k*LD + pc[b]];
#pragma unroll
            for (int a = 0; a < 4; a++)
#pragma unroll
                for (int b = 0; b < 4; b++) acc[a][b] += av[a]*bv[b];
        }
        __syncthreads();
#pragma unroll
        for (int a = 0; a < 4; a++)
#pragma unroll
            for (int b = 0; b < 4; b++)
                sA[(i0+a)*LD + j0 + b] =
                    acc[a][b] * Mg[(i0+a)*64 + (j0+b)];
    }
    __syncthreads();

    // rho_out = 2 * Of @ Of^T ; ener1 = sum(rho_out * H)
    {
        float acc[4][4];
#pragma unroll
        for (int a = 0; a < 4; a++)
#pragma unroll
            for (int b = 0; b < 4; b++) acc[a][b] = 0.0f;
#pragma unroll 4
        for (int k = 0; k < BB; k++) {
            float av[4], bv[4];
#pragma unroll
            for (int a = 0; a < 4; a++) av[a] = sA[(i0+a)*LD + k];
#pragma unroll
            for (int b = 0; b < 4; b++) bv[b] = sA[(j0+b)*LD + k];
#pragma unroll
            for (int a = 0; a < 4; a++)
#pragma unroll
                for (int b = 0; b < 4; b++) acc[a][b] += av[a]*bv[b];
        }
        float e1 = 0.0f;
#pragma unroll
        for (int a = 0; a < 4; a++)
#pragma unroll
            for (int b = 0; b < 4; b++) {
                float rr = 2.0f * acc[a][b];
                int idx = (i0+a)*64 + (j0+b);
                out[OFF_RHO + (size_t)g*BB*BB + idx] = rr;
                e1 += rr * Hg[idx];
            }
        red[t] = e1;
    }
    __syncthreads();
    for (int o = 128; o; o >>= 1) {
        if (t < o) red[t] += red[t + o];
        __syncthreads();
    }
    if (t == 0) out[OFF_EELEC + g] = red[0] + s_ener2;
}

// ---------------- launch ----------------
extern "C" void kernel_launch(void* const* d_in, const int* in_sizes, int n_in,
                              void* d_out, int out_size)
{
    const float* net   = (const float*)d_in[0];
    const float* rotT  = (const float*)d_in[1];
    const float* S     = (const float*)d_in[2];
    const float* G     = (const float*)d_in[3];
    const float* rho   = (const float*)d_in[4];
    const float* qn    = (const float*)d_in[5];
    const float* mask  = (const float*)d_in[6];
    const float* phiS  = (const float*)d_in[7];
    const float* zc    = (const float*)d_in[8];
    const float* rv    = (const float*)d_in[9];
    const int* g_rot   = (const int*)d_in[10];
    const int* g_oper  = (const int*)d_in[11];
    const int* g_rep   = (const int*)d_in[12];
    const int* g_seg   = (const int*)d_in[13];
    float* out = (float*)d_out;

    const int smem = 3 * LD * BB * (int)sizeof(float);   // 49,920 B > 48K default
    cudaFuncSetAttribute(k_geom, cudaFuncAttributeMaxDynamicSharedMemorySize, smem);

    k_rot    <<<(R_CNT + 255)/256, 256>>>(net, rotT, g_rot);
    k_misc   <<<4, 256>>>(zc, rv, out);
    k_hgather<<<(NGEO*BB*BB)/256, 256>>>(g_oper, out);
    k_erep   <<<(EREPN + 255)/256, 256>>>(net, g_rep, g_seg, out);
    k_geom   <<<NGEO, 256, smem>>>(S, G, rho, qn, mask, phiS, out);
}

// round 6
// speedup vs baseline: 1.0028x; 1.0028x over previous
#include <cuda_runtime.h>
#include <math.h>

// ---------------- problem constants ----------------
#define R_CNT   1000000
#define NGEO    1024
#define BB      64
#define LD      65            // padded row stride (bank-conflict-free columns)
#define NEL     7
#define EREPN   2000000
#define NNET    4000000
#define ROT_LEN (2 + R_CNT*9)
#define NSWEEP_MAX 30

// ---------------- output layout (flattened tuple) ----------------
#define OFF_H     0
#define OFF_DQ    (NGEO*BB*BB)               // 4194304
#define OFF_EREP  (OFF_DQ + NGEO*BB)         // 4259840
#define OFF_EORB  (OFF_EREP + NGEO)          // 4260864
#define OFF_RHO   (OFF_EORB + NGEO*BB)       // 4326400
#define OFF_EELEC (OFF_RHO + NGEO*BB*BB)     // 8520704
#define OFF_EREF  (OFF_EELEC + NGEO)         // 8521728

// scratch: rotated sp-block table (36 MB)
__device__ float g_rot_out[ROT_LEN];

// ---------------- stage 1: rotation (SMEM-staged coalesced T reads) ----------------
__global__ void __launch_bounds__(256) k_rot(
    const float* __restrict__ net,
    const float* __restrict__ T,
    const int*   __restrict__ gidx)
{
    __shared__ float sT[256 * 27];   // 27 KB staging
    const int tid  = threadIdx.x;
    const int base = blockIdx.x * 256;          // first r of this block
    const int cnt  = min(256, R_CNT - base);    // rows this block owns
    if (cnt <= 0) return;

    // coalesced stage: cnt*27 contiguous floats
    const float* Tb = T + (size_t)base * 27;
    for (int i = tid; i < cnt * 27; i += 256) sT[i] = Tb[i];
    __syncthreads();

    if (tid >= cnt) return;
    const int r = base + tid;
    if (r == 0) { g_rot_out[0] = 0.0f; g_rot_out[1] = 1.0f; }
    float v0 = net[gidx[3*r + 0]];
    float v1 = net[gidx[3*r + 1]];
    float v2 = net[gidx[3*r + 2]];
    const float* t = sT + tid * 27;   // stride 27 vs 32 banks: conflict-free
    float* o = g_rot_out + 2 + (size_t)r * 9;
#pragma unroll
    for (int i = 0; i < 9; i++)
        o[i] = t[3*i + 0] * v0 + t[3*i + 1] * v1 + t[3*i + 2] * v2;
}

// ---------------- stage 2: H gather ----------------
__global__ void k_hgather(const int* __restrict__ gop, float* __restrict__ out)
{
    int i = blockIdx.x * blockDim.x + threadIdx.x;
    if (i < NGEO*BB*BB) out[OFF_H + i] = g_rot_out[gop[i]];
}

// ---------------- misc: zero Erep, compute Eref ----------------
__global__ void k_misc(const float* __restrict__ zc,
                       const float* __restrict__ rv,
                       float* __restrict__ out)
{
    int i = blockIdx.x * blockDim.x + threadIdx.x;
    if (i < NGEO) out[OFF_EREP + i] = 0.0f;
    if (i == 0) {
        float s = 0.0f;
        for (int e = 0; e < NEL; e++) s += zc[e] * rv[e];
        out[OFF_EREF] = s;
    }
}

// ---------------- stage 3: repulsive segment sum ----------------
__global__ void k_erep(const float* __restrict__ net,
                       const int*   __restrict__ gr,
                       const int*   __restrict__ seg,
                       float* __restrict__ out)
{
    int i = blockIdx.x * blockDim.x + threadIdx.x;
    if (i >= EREPN) return;
    int lane = threadIdx.x & 31;
    float v = net[gr[i]];
    int   s = seg[i];
    // inclusive segmented warp scan (segments sorted -> contiguous runs)
#pragma unroll
    for (int off = 1; off < 32; off <<= 1) {
        float nv = __shfl_up_sync(0xffffffffu, v, off);
        int   ns = __shfl_up_sync(0xffffffffu, s, off);
        if (lane >= off && ns == s) v += nv;
    }
    int nxt = __shfl_down_sync(0xffffffffu, s, 1);
    if (lane == 31 || s != nxt)
        atomicAdd(&out[OFF_EREP + s], v);
}

// ---------------- stage 4: per-geometry dense stage ----------------
__global__ void __launch_bounds__(256) k_geom(
    const float* __restrict__ S,   const float* __restrict__ G,
    const float* __restrict__ rho, const float* __restrict__ qn,
    const float* __restrict__ mask,const float* __restrict__ phiS,
    float* __restrict__ out)
{
    extern __shared__ float sm[];
    float* sA = sm;                // working matrix (F -> fockp -> A -> orb)
    float* sB = sm + LD*BB;        // S -> T(=F*P) -> V(eigvecs)
    float* sP = sm + 2*LD*BB;      // phiS
    __shared__ float dq[BB], epv[BB], eig[BB];
    __shared__ float cc[32], ssn[32];
    __shared__ int   ppx[32], qqx[32], perm[BB];
    __shared__ float red[256];
    __shared__ float s_ener2;
    __shared__ float s_thresh;     // 2.5e-11 * ||A||_F^2 (invariant under rotations)
    __shared__ int   s_done;

    const int g = blockIdx.x;
    const int t = threadIdx.x;
    const int w = t >> 5, lane = t & 31;
    const int ty = t >> 4, tx = t & 15;
    const int i0 = ty * 4, j0 = tx * 4;

    const float* Sg = S    + (size_t)g*BB*BB;
    const float* Gg = G    + (size_t)g*BB*BB;
    const float* Rg = rho  + (size_t)g*BB*BB;
    const float* Mg = mask + (size_t)g*BB*BB;
    const float* Pg = phiS + (size_t)g*BB*BB;
    const float* Hg = out + OFF_H + (size_t)g*BB*BB;

    // load S -> sB, phiS -> sP
#pragma unroll
    for (int m = 0; m < 16; m++) {
        int idx = t + m*256; int i = idx >> 6, j = idx & 63;
        sB[i*LD + j] = Sg[idx];
        sP[i*LD + j] = Pg[idx];
    }
    __syncthreads();

    // dQ[i] = qn[i] - sum_j rho[i][j]*S[i][j]
    for (int i = w; i < BB; i += 8) {
        float a = Rg[i*64 + lane]      * sB[i*LD + lane]
                + Rg[i*64 + 32 + lane] * sB[i*LD + 32 + lane];
#pragma unroll
        for (int o = 16; o; o >>= 1) a += __shfl_down_sync(0xffffffffu, a, o);
        if (lane == 0) dq[i] = qn[g*64 + i] - a;
    }
    __syncthreads();

    // ep = G @ dQ
    for (int i = w; i < BB; i += 8) {
        float a = Gg[i*64 + lane]      * dq[lane]
                + Gg[i*64 + 32 + lane] * dq[lane + 32];
#pragma unroll
        for (int o = 16; o; o >>= 1) a += __shfl_down_sync(0xffffffffu, a, o);
        if (lane == 0) epv[i] = a;
    }
    __syncthreads();

    // ener2 = 0.5 * dQ . ep
    if (w == 0) {
        float a = dq[lane]*epv[lane] + dq[lane+32]*epv[lane+32];
#pragma unroll
        for (int o = 16; o; o >>= 1) a += __shfl_down_sync(0xffffffffu, a, o);
        if (lane == 0) s_ener2 = 0.5f * a;
    }
    if (t < 64) out[OFF_DQ + g*64 + t] = dq[t];

    // F = H - 0.5*S*(ep_i + ep_j)  -> sA
#pragma unroll
    for (int m = 0; m < 16; m++) {
        int idx = t + m*256; int i = idx >> 6, j = idx & 63;
        sA[i*LD + j] = Hg[idx] - 0.5f * sB[i*LD + j] * (epv[i] + epv[j]);
    }
    __syncthreads();

    // T = F @ P  -> sB (overwrites S; no one reads S anymore)
    {
        float acc[4][4];
#pragma unroll
        for (int a = 0; a < 4; a++)
#pragma unroll
            for (int b = 0; b < 4; b++) acc[a][b] = 0.0f;
#pragma unroll 4
        for (int k = 0; k < BB; k++) {
            float av[4], bv[4];
#pragma unroll
            for (int a = 0; a < 4; a++) av[a] = sA[(i0+a)*LD + k];
#pragma unroll
            for (int b = 0; b < 4; b++) bv[b] = sP[k*LD + j0 + b];
#pragma unroll
            for (int a = 0; a < 4; a++)
#pragma unroll
                for (int b = 0; b < 4; b++) acc[a][b] += av[a]*bv[b];
        }
        __syncthreads();
#pragma unroll
        for (int a = 0; a < 4; a++)
#pragma unroll
            for (int b = 0; b < 4; b++) sB[(i0+a)*LD + j0 + b] = acc[a][b];
    }
    __syncthreads();

    // fockp = P^T @ T  -> sA
    {
        float acc[4][4];
#pragma unroll
        for (int a = 0; a < 4; a++)
#pragma unroll
            for (int b = 0; b < 4; b++) acc[a][b] = 0.0f;
#pragma unroll 4
        for (int k = 0; k < BB; k++) {
            float av[4], bv[4];
#pragma unroll
            for (int a = 0; a < 4; a++) av[a] = sP[k*LD + i0 + a];
#pragma unroll
            for (int b = 0; b < 4; b++) bv[b] = sB[k*LD + j0 + b];
#pragma unroll
            for (int a = 0; a < 4; a++)
#pragma unroll
                for (int b = 0; b < 4; b++) acc[a][b] += av[a]*bv[b];
        }
        __syncthreads();
#pragma unroll
        for (int a = 0; a < 4; a++)
#pragma unroll
            for (int b = 0; b < 4; b++) sA[(i0+a)*LD + j0 + b] = acc[a][b];
    }
    __syncthreads();

    // ||A||_F^2 (invariant under the Jacobi rotations) -> s_thresh
    {
        float nrm = 0.0f;
#pragma unroll
        for (int a = 0; a < 4; a++)
#pragma unroll
            for (int b = 0; b < 4; b++) {
                float v = sA[(i0+a)*LD + j0 + b];
                nrm += v*v;
            }
        red[t] = nrm;
    }
    // V = I  -> sB  (overlap with reduction barrier structure)
#pragma unroll
    for (int m = 0; m < 16; m++) {
        int idx = t + m*256; int i = idx >> 6, j = idx & 63;
        sB[i*LD + j] = (i == j) ? 1.0f : 0.0f;
    }
    __syncthreads();
    for (int o = 128; o; o >>= 1) {
        if (t < o) red[t] += red[t + o];
        __syncthreads();
    }
    if (t == 0) { s_thresh = 2.5e-11f * red[0]; s_done = 0; }
    __syncthreads();

    // ----- parallel cyclic Jacobi: A in sA, V in sB -----
    for (int sweep = 0; sweep < NSWEEP_MAX; sweep++) {
        for (int r = 0; r < 63; r++) {
            if (t < 32) {
                int p, q;
                if (t == 0) { p = 63; q = r; }
                else { p = (r + t) % 63; q = (r + 63 - t) % 63; }
                if (p > q) { int tmp = p; p = q; q = tmp; }
                float app = sA[p*LD + p], aqq = sA[q*LD + q];
                float apq = 0.5f * (sA[p*LD + q] + sA[q*LD + p]);  // symmetrized pivot
                float c = 1.0f, s = 0.0f;
                if (fabsf(apq) > 1e-20f) {
                    float tau = (aqq - app) / (2.0f * apq);
                    float tt  = copysignf(1.0f, tau) / (fabsf(tau) + sqrtf(1.0f + tau*tau));
                    c = rsqrtf(1.0f + tt*tt);
                    s = tt * c;
                }
                cc[t] = c; ssn[t] = s; ppx[t] = p; qqx[t] = q;
            }
            __syncthreads();
            // row updates: A <- R^T A
#pragma unroll
            for (int m = 0; m < 8; m++) {
                int u = t + m*256; int k = u >> 6, j = u & 63;
                int p = ppx[k], q = qqx[k];
                float c = cc[k], s = ssn[k];
                float apj = sA[p*LD + j], aqj = sA[q*LD + j];
                sA[p*LD + j] = c*apj - s*aqj;
                sA[q*LD + j] = s*apj + c*aqj;
            }
            __syncthreads();
            // column updates: A <- A R ; V <- V R
#pragma unroll
            for (int m = 0; m < 8; m++) {
                int u = t + m*256; int k = u >> 6, i = u & 63;
                int p = ppx[k], q = qqx[k];
                float c = cc[k], s = ssn[k];
                float aip = sA[i*LD + p], aiq = sA[i*LD + q];
                sA[i*LD + p] = c*aip - s*aiq;
                sA[i*LD + q] = s*aip + c*aiq;
                float vip = sB[i*LD + p], viq = sB[i*LD + q];
                sB[i*LD + p] = c*vip - s*viq;
                sB[i*LD + q] = s*vip + c*viq;
            }
            __syncthreads();
        }
        // ---- convergence check vs invariant ||A||_F^2 (from sweep 7 on) ----
        if (sweep >= 6) {
            float offs = 0.0f;
#pragma unroll
            for (int a = 0; a < 4; a++)
#pragma unroll
                for (int b = 0; b < 4; b++) {
                    int i = i0 + a, j = j0 + b;
                    if (i != j) { float v = sA[i*LD + j]; offs += v*v; }
                }
            red[t] = offs;
            __syncthreads();
            for (int o = 128; o; o >>= 1) {
                if (t < o) red[t] += red[t + o];
                __syncthreads();
            }
            // off_F < 5e-6 * ||A||_F  -> done
            if (t == 0 && red[0] < s_thresh) s_done = 1;
            __syncthreads();
            if (s_done) break;
        }
    }

    // ----- sort eigenvalues ascending (tie-break by index), build perm -----
    if (t < 64) eig[t] = sA[t*LD + t];
    __syncthreads();
    if (t < 64) {
        float v = eig[t];
        int rk = 0;
        for (int j = 0; j < 64; j++) {
            float u = eig[j];
            rk += (u < v) || (u == v && j < t);
        }
        perm[rk] = t;
        out[OFF_EORB + g*64 + rk] = v;
    }
    __syncthreads();

    // orb = P @ V[:, perm], masked -> sA
    {
        int pc[4];
#pragma unroll
        for (int b = 0; b < 4; b++) pc[b] = perm[j0 + b];
        float acc[4][4];
#pragma unroll
        for (int a = 0; a < 4; a++)
#pragma unroll
            for (int b = 0; b < 4; b++) acc[a][b] = 0.0f;
#pragma unroll 4
        for (int k = 0; k < BB; k++) {
            float av[4], bv[4];
#pragma unroll
            for (int a = 0; a < 4; a++) av[a] = sP[(i0+a)*LD + k];
#pragma unroll
            for (int b = 0; b < 4; b++) bv[b] = sB[k*LD + pc[b]];
#pragma unroll
            for (int a = 0; a < 4; a++)
#pragma unroll
                for (int b = 0; b < 4; b++) acc[a][b] += av[a]*bv[b];
        }
        __syncthreads();
#pragma unroll
        for (int a = 0; a < 4; a++)
#pragma unroll
            for (int b = 0; b < 4; b++)
                sA[(i0+a)*LD + j0 + b] =
                    acc[a][b] * Mg[(i0+a)*64 + (j0+b)];
    }
    __syncthreads();

    // rho_out = 2 * Of @ Of^T ; ener1 = sum(rho_out * H)
    {
        float acc[4][4];
#pragma unroll
        for (int a = 0; a < 4; a++)
#pragma unroll
            for (int b = 0; b < 4; b++) acc[a][b] = 0.0f;
#pragma unroll 4
        for (int k = 0; k < BB; k++) {
            float av[4], bv[4];
#pragma unroll
            for (int a = 0; a < 4; a++) av[a] = sA[(i0+a)*LD + k];
#pragma unroll
            for (int b = 0; b < 4; b++) bv[b] = sA[(j0+b)*LD + k];
#pragma unroll
            for (int a = 0; a < 4; a++)
#pragma unroll
                for (int b = 0; b < 4; b++) acc[a][b] += av[a]*bv[b];
        }
        float e1 = 0.0f;
#pragma unroll
        for (int a = 0; a < 4; a++)
#pragma unroll
            for (int b = 0; b < 4; b++) {
                float rr = 2.0f * acc[a][b];
                int idx = (i0+a)*64 + (j0+b);
                out[OFF_RHO + (size_t)g*BB*BB + idx] = rr;
                e1 += rr * Hg[idx];
            }
        red[t] = e1;
    }
    __syncthreads();
    for (int o = 128; o; o >>= 1) {
        if (t < o) red[t] += red[t + o];
        __syncthreads();
    }
    if (t == 0) out[OFF_EELEC + g] = red[0] + s_ener2;
}

// ---------------- launch ----------------
extern "C" void kernel_launch(void* const* d_in, const int* in_sizes, int n_in,
                              void* d_out, int out_size)
{
    const float* net   = (const float*)d_in[0];
    const float* rotT  = (const float*)d_in[1];
    const float* S     = (const float*)d_in[2];
    const float* G     = (const float*)d_in[3];
    const float* rho   = (const float*)d_in[4];
    const float* qn    = (const float*)d_in[5];
    const float* mask  = (const float*)d_in[6];
    const float* phiS  = (const float*)d_in[7];
    const float* zc    = (const float*)d_in[8];
    const float* rv    = (const float*)d_in[9];
    const int* g_rot   = (const int*)d_in[10];
    const int* g_oper  = (const int*)d_in[11];
    const int* g_rep   = (const int*)d_in[12];
    const int* g_seg   = (const int*)d_in[13];
    float* out = (float*)d_out;

    const int smem = 3 * LD * BB * (int)sizeof(float);   // 49,920 B > 48K default
    cudaFuncSetAttribute(k_geom, cudaFuncAttributeMaxDynamicSharedMemorySize, smem);

    k_rot    <<<(R_CNT + 255)/256, 256>>>(net, rotT, g_rot);
    k_misc   <<<4, 256>>>(zc, rv, out);
    k_hgather<<<(NGEO*BB*BB)/256, 256>>>(g_oper, out);
    k_erep   <<<(EREPN + 255)/256, 256>>>(net, g_rep, g_seg, out);
    k_geom   <<<NGEO, 256, smem>>>(S, G, rho, qn, mask, phiS, out);
}

// round 7
// speedup vs baseline: 1.0037x; 1.0010x over previous
#include <cuda_runtime.h>
#include <math.h>

// ---------------- problem constants ----------------
#define R_CNT   1000000
#define NGEO    1024
#define BB      64
#define LD      65            // padded row stride (bank-conflict-free columns)
#define NEL     7
#define EREPN   2000000
#define NNET    4000000
#define ROT_LEN (2 + R_CNT*9)
#define NSWEEP_MAX 30

// ---------------- output layout (flattened tuple) ----------------
#define OFF_H     0
#define OFF_DQ    (NGEO*BB*BB)               // 4194304
#define OFF_EREP  (OFF_DQ + NGEO*BB)         // 4259840
#define OFF_EORB  (OFF_EREP + NGEO)          // 4260864
#define OFF_RHO   (OFF_EORB + NGEO*BB)       // 4326400
#define OFF_EELEC (OFF_RHO + NGEO*BB*BB)     // 8520704
#define OFF_EREF  (OFF_EELEC + NGEO)         // 8521728

// scratch: rotated sp-block table (36 MB)
__device__ float g_rot_out[ROT_LEN];

// ---------------- stage 1: rotation (SMEM-staged coalesced T reads) ----------------
__global__ void __launch_bounds__(256) k_rot(
    const float* __restrict__ net,
    const float* __restrict__ T,
    const int*   __restrict__ gidx)
{
    __shared__ float sT[256 * 27];   // 27 KB staging
    const int tid  = threadIdx.x;
    const int base = blockIdx.x * 256;          // first r of this block
    const int cnt  = min(256, R_CNT - base);    // rows this block owns
    if (cnt <= 0) return;

    // coalesced stage: cnt*27 contiguous floats
    const float* Tb = T + (size_t)base * 27;
    for (int i = tid; i < cnt * 27; i += 256) sT[i] = Tb[i];
    __syncthreads();

    if (tid >= cnt) return;
    const int r = base + tid;
    if (r == 0) { g_rot_out[0] = 0.0f; g_rot_out[1] = 1.0f; }
    float v0 = net[gidx[3*r + 0]];
    float v1 = net[gidx[3*r + 1]];
    float v2 = net[gidx[3*r + 2]];
    const float* t = sT + tid * 27;   // stride 27 vs 32 banks: conflict-free
    float* o = g_rot_out + 2 + (size_t)r * 9;
#pragma unroll
    for (int i = 0; i < 9; i++)
        o[i] = t[3*i + 0] * v0 + t[3*i + 1] * v1 + t[3*i + 2] * v2;
}

// ---------------- stage 2: H gather ----------------
__global__ void k_hgather(const int* __restrict__ gop, float* __restrict__ out)
{
    int i = blockIdx.x * blockDim.x + threadIdx.x;
    if (i < NGEO*BB*BB) out[OFF_H + i] = g_rot_out[gop[i]];
}

// ---------------- misc: zero Erep, compute Eref ----------------
__global__ void k_misc(const float* __restrict__ zc,
                       const float* __restrict__ rv,
                       float* __restrict__ out)
{
    int i = blockIdx.x * blockDim.x + threadIdx.x;
    if (i < NGEO) out[OFF_EREP + i] = 0.0f;
    if (i == 0) {
        float s = 0.0f;
        for (int e = 0; e < NEL; e++) s += zc[e] * rv[e];
        out[OFF_EREF] = s;
    }
}

// ---------------- stage 3: repulsive segment sum ----------------
__global__ void k_erep(const float* __restrict__ net,
                       const int*   __restrict__ gr,
                       const int*   __restrict__ seg,
                       float* __restrict__ out)
{
    int i = blockIdx.x * blockDim.x + threadIdx.x;
    if (i >= EREPN) return;
    int lane = threadIdx.x & 31;
    float v = net[gr[i]];
    int   s = seg[i];
    // inclusive segmented warp scan (segments sorted -> contiguous runs)
#pragma unroll
    for (int off = 1; off < 32; off <<= 1) {
        float nv = __shfl_up_sync(0xffffffffu, v, off);
        int   ns = __shfl_up_sync(0xffffffffu, s, off);
        if (lane >= off && ns == s) v += nv;
    }
    int nxt = __shfl_down_sync(0xffffffffu, s, 1);
    if (lane == 31 || s != nxt)
        atomicAdd(&out[OFF_EREP + s], v);
}

// ---------------- stage 4: per-geometry dense stage ----------------
__global__ void __launch_bounds__(256) k_geom(
    const float* __restrict__ S,   const float* __restrict__ G,
    const float* __restrict__ rho, const float* __restrict__ qn,
    const float* __restrict__ mask,const float* __restrict__ phiS,
    float* __restrict__ out)
{
    extern __shared__ float sm[];
    float* sA = sm;                // working matrix (F -> fockp -> A -> orb)
    float* sB = sm + LD*BB;        // S -> T(=F*P) -> V(eigvecs)
    float* sP = sm + 2*LD*BB;      // phiS
    __shared__ float dq[BB], epv[BB], eig[BB];
    __shared__ float cc[32], ssn[32];
    __shared__ int   ppx[32], qqx[32], perm[BB];
    __shared__ float red[256];
    __shared__ float s_ener2;
    __shared__ float s_thresh;     // 2.5e-9 * ||A||_F^2 (invariant under rotations)
    __shared__ int   s_done;

    const int g = blockIdx.x;
    const int t = threadIdx.x;
    const int w = t >> 5, lane = t & 31;
    const int ty = t >> 4, tx = t & 15;
    const int i0 = ty * 4, j0 = tx * 4;

    const float* Sg = S    + (size_t)g*BB*BB;
    const float* Gg = G    + (size_t)g*BB*BB;
    const float* Rg = rho  + (size_t)g*BB*BB;
    const float* Mg = mask + (size_t)g*BB*BB;
    const float* Pg = phiS + (size_t)g*BB*BB;
    const float* Hg = out + OFF_H + (size_t)g*BB*BB;

    // load S -> sB, phiS -> sP
#pragma unroll
    for (int m = 0; m < 16; m++) {
        int idx = t + m*256; int i = idx >> 6, j = idx & 63;
        sB[i*LD + j] = Sg[idx];
        sP[i*LD + j] = Pg[idx];
    }
    __syncthreads();

    // dQ[i] = qn[i] - sum_j rho[i][j]*S[i][j]
    for (int i = w; i < BB; i += 8) {
        float a = Rg[i*64 + lane]      * sB[i*LD + lane]
                + Rg[i*64 + 32 + lane] * sB[i*LD + 32 + lane];
#pragma unroll
        for (int o = 16; o; o >>= 1) a += __shfl_down_sync(0xffffffffu, a, o);
        if (lane == 0) dq[i] = qn[g*64 + i] - a;
    }
    __syncthreads();

    // ep = G @ dQ
    for (int i = w; i < BB; i += 8) {
        float a = Gg[i*64 + lane]      * dq[lane]
                + Gg[i*64 + 32 + lane] * dq[lane + 32];
#pragma unroll
        for (int o = 16; o; o >>= 1) a += __shfl_down_sync(0xffffffffu, a, o);
        if (lane == 0) epv[i] = a;
    }
    __syncthreads();

    // ener2 = 0.5 * dQ . ep
    if (w == 0) {
        float a = dq[lane]*epv[lane] + dq[lane+32]*epv[lane+32];
#pragma unroll
        for (int o = 16; o; o >>= 1) a += __shfl_down_sync(0xffffffffu, a, o);
        if (lane == 0) s_ener2 = 0.5f * a;
    }
    if (t < 64) out[OFF_DQ + g*64 + t] = dq[t];

    // F = H - 0.5*S*(ep_i + ep_j)  -> sA
#pragma unroll
    for (int m = 0; m < 16; m++) {
        int idx = t + m*256; int i = idx >> 6, j = idx & 63;
        sA[i*LD + j] = Hg[idx] - 0.5f * sB[i*LD + j] * (epv[i] + epv[j]);
    }
    __syncthreads();

    // T = F @ P  -> sB (overwrites S; no one reads S anymore)
    {
        float acc[4][4];
#pragma unroll
        for (int a = 0; a < 4; a++)
#pragma unroll
            for (int b = 0; b < 4; b++) acc[a][b] = 0.0f;
#pragma unroll 4
        for (int k = 0; k < BB; k++) {
            float av[4], bv[4];
#pragma unroll
            for (int a = 0; a < 4; a++) av[a] = sA[(i0+a)*LD + k];
#pragma unroll
            for (int b = 0; b < 4; b++) bv[b] = sP[k*LD + j0 + b];
#pragma unroll
            for (int a = 0; a < 4; a++)
#pragma unroll
                for (int b = 0; b < 4; b++) acc[a][b] += av[a]*bv[b];
        }
        __syncthreads();
#pragma unroll
        for (int a = 0; a < 4; a++)
#pragma unroll
            for (int b = 0; b < 4; b++) sB[(i0+a)*LD + j0 + b] = acc[a][b];
    }
    __syncthreads();

    // fockp = P^T @ T  -> sA
    {
        float acc[4][4];
#pragma unroll
        for (int a = 0; a < 4; a++)
#pragma unroll
            for (int b = 0; b < 4; b++) acc[a][b] = 0.0f;
#pragma unroll 4
        for (int k = 0; k < BB; k++) {
            float av[4], bv[4];
#pragma unroll
            for (int a = 0; a < 4; a++) av[a] = sP[k*LD + i0 + a];
#pragma unroll
            for (int b = 0; b < 4; b++) bv[b] = sB[k*LD + j0 + b];
#pragma unroll
            for (int a = 0; a < 4; a++)
#pragma unroll
                for (int b = 0; b < 4; b++) acc[a][b] += av[a]*bv[b];
        }
        __syncthreads();
#pragma unroll
        for (int a = 0; a < 4; a++)
#pragma unroll
            for (int b = 0; b < 4; b++) sA[(i0+a)*LD + j0 + b] = acc[a][b];
    }
    __syncthreads();

    // ||A||_F^2 (invariant under the Jacobi rotations) -> s_thresh
    {
        float nrm = 0.0f;
#pragma unroll
        for (int a = 0; a < 4; a++)
#pragma unroll
            for (int b = 0; b < 4; b++) {
                float v = sA[(i0+a)*LD + j0 + b];
                nrm += v*v;
            }
        red[t] = nrm;
    }
    // V = I  -> sB  (overlap with reduction barrier structure)
#pragma unroll
    for (int m = 0; m < 16; m++) {
        int idx = t + m*256; int i = idx >> 6, j = idx & 63;
        sB[i*LD + j] = (i == j) ? 1.0f : 0.0f;
    }
    __syncthreads();
    for (int o = 128; o; o >>= 1) {
        if (t < o) red[t] += red[t + o];
        __syncthreads();
    }
    if (t == 0) { s_thresh = 2.5e-9f * red[0]; s_done = 0; }
    __syncthreads();

    // ----- parallel cyclic Jacobi: A in sA, V in sB -----
    for (int sweep = 0; sweep < NSWEEP_MAX; sweep++) {
        for (int r = 0; r < 63; r++) {
            if (t < 32) {
                int p, q;
                if (t == 0) { p = 63; q = r; }
                else { p = (r + t) % 63; q = (r + 63 - t) % 63; }
                if (p > q) { int tmp = p; p = q; q = tmp; }
                float app = sA[p*LD + p], aqq = sA[q*LD + q];
                float apq = 0.5f * (sA[p*LD + q] + sA[q*LD + p]);  // symmetrized pivot
                float c = 1.0f, s = 0.0f;
                if (fabsf(apq) > 1e-20f) {
                    float tau = (aqq - app) / (2.0f * apq);
                    float tt  = copysignf(1.0f, tau) / (fabsf(tau) + sqrtf(1.0f + tau*tau));
                    c = rsqrtf(1.0f + tt*tt);
                    s = tt * c;
                }
                cc[t] = c; ssn[t] = s; ppx[t] = p; qqx[t] = q;
            }
            __syncthreads();
            // row updates: A <- R^T A
#pragma unroll
            for (int m = 0; m < 8; m++) {
                int u = t + m*256; int k = u >> 6, j = u & 63;
                int p = ppx[k], q = qqx[k];
                float c = cc[k], s = ssn[k];
                float apj = sA[p*LD + j], aqj = sA[q*LD + j];
                sA[p*LD + j] = c*apj - s*aqj;
                sA[q*LD + j] = s*apj + c*aqj;
            }
            __syncthreads();
            // column updates: A <- A R ; V <- V R
#pragma unroll
            for (int m = 0; m < 8; m++) {
                int u = t + m*256; int k = u >> 6, i = u & 63;
                int p = ppx[k], q = qqx[k];
                float c = cc[k], s = ssn[k];
                float aip = sA[i*LD + p], aiq = sA[i*LD + q];
                sA[i*LD + p] = c*aip - s*aiq;
                sA[i*LD + q] = s*aip + c*aiq;
                float vip = sB[i*LD + p], viq = sB[i*LD + q];
                sB[i*LD + p] = c*vip - s*viq;
                sB[i*LD + q] = s*vip + c*viq;
            }
            __syncthreads();
        }
        // ---- convergence check vs invariant ||A||_F^2 (from sweep 6 on) ----
        if (sweep >= 5) {
            float offs = 0.0f;
#pragma unroll
            for (int a = 0; a < 4; a++)
#pragma unroll
                for (int b = 0; b < 4; b++) {
                    int i = i0 + a, j = j0 + b;
                    if (i != j) { float v = sA[i*LD + j]; offs += v*v; }
                }
            red[t] = offs;
            __syncthreads();
            for (int o = 128; o; o >>= 1) {
                if (t < o) red[t] += red[t + o];
                __syncthreads();
            }
            // off_F < 5e-5 * ||A||_F  -> done
            if (t == 0 && red[0] < s_thresh) s_done = 1;
            __syncthreads();
            if (s_done) break;
        }
    }

    // ----- sort eigenvalues ascending (tie-break by index), build perm -----
    if (t < 64) eig[t] = sA[t*LD + t];
    __syncthreads();
    if (t < 64) {
        float v = eig[t];
        int rk = 0;
        for (int j = 0; j < 64; j++) {
            float u = eig[j];
            rk += (u < v) || (u == v && j < t);
        }
        perm[rk] = t;
        out[OFF_EORB + g*64 + rk] = v;
    }
    __syncthreads();

    // orb = P @ V[:, perm], masked -> sA
    {
        int pc[4];
#pragma unroll
        for (int b = 0; b < 4; b++) pc[b] = perm[j0 + b];
        float acc[4][4];
#pragma unroll
        for (int a = 0; a < 4; a++)
#pragma unroll
            for (int b = 0; b < 4; b++) acc[a][b] = 0.0f;
#pragma unroll 4
        for (int k = 0; k < BB; k++) {
            float av[4], bv[4];
#pragma unroll
            for (int a = 0; a < 4; a++) av[a] = sP[(i0+a)*LD + k];
#pragma unroll
            for (int b = 0; b < 4; b++) bv[b] = sB[k*LD + pc[b]];
#pragma unroll
            for (int a = 0; a < 4; a++)
#pragma unroll
                for (int b = 0; b < 4; b++) acc[a][b] += av[a]*bv[b];
        }
        __syncthreads();
#pragma unroll
        for (int a = 0; a < 4; a++)
#pragma unroll
            for (int b = 0; b < 4; b++)
                sA[(i0+a)*LD + j0 + b] =
                    acc[a][b] * Mg[(i0+a)*64 + (j0+b)];
    }
    __syncthreads();

    // rho_out = 2 * Of @ Of^T ; ener1 = sum(rho_out * H)
    {
        float acc[4][4];
#pragma unroll
        for (int a = 0; a < 4; a++)
#pragma unroll
            for (int b = 0; b < 4; b++) acc[a][b] = 0.0f;
#pragma unroll 4
        for (int k = 0; k < BB; k++) {
            float av[4], bv[4];
#pragma unroll
            for (int a = 0; a < 4; a++) av[a] = sA[(i0+a)*LD + k];
#pragma unroll
            for (int b = 0; b < 4; b++) bv[b] = sA[(j0+b)*LD + k];
#pragma unroll
            for (int a = 0; a < 4; a++)
#pragma unroll
                for (int b = 0; b < 4; b++) acc[a][b] += av[a]*bv[b];
        }
        float e1 = 0.0f;
#pragma unroll
        for (int a = 0; a < 4; a++)
#pragma unroll
            for (int b = 0; b < 4; b++) {
                float rr = 2.0f * acc[a][b];
                int idx = (i0+a)*64 + (j0+b);
                out[OFF_RHO + (size_t)g*BB*BB + idx] = rr;
                e1 += rr * Hg[idx];
            }
        red[t] = e1;
    }
    __syncthreads();
    for (int o = 128; o; o >>= 1) {
        if (t < o) red[t] += red[t + o];
        __syncthreads();
    }
    if (t == 0) out[OFF_EELEC + g] = red[0] + s_ener2;
}

// ---------------- launch ----------------
extern "C" void kernel_launch(void* const* d_in, const int* in_sizes, int n_in,
                              void* d_out, int out_size)
{
    const float* net   = (const float*)d_in[0];
    const float* rotT  = (const float*)d_in[1];
    const float* S     = (const float*)d_in[2];
    const float* G     = (const float*)d_in[3];
    const float* rho   = (const float*)d_in[4];
    const float* qn    = (const float*)d_in[5];
    const float* mask  = (const float*)d_in[6];
    const float* phiS  = (const float*)d_in[7];
    const float* zc    = (const float*)d_in[8];
    const float* rv    = (const float*)d_in[9];
    const int* g_rot   = (const int*)d_in[10];
    const int* g_oper  = (const int*)d_in[11];
    const int* g_rep   = (const int*)d_in[12];
    const int* g_seg   = (const int*)d_in[13];
    float* out = (float*)d_out;

    const int smem = 3 * LD * BB * (int)sizeof(float);   // 49,920 B > 48K default
    cudaFuncSetAttribute(k_geom, cudaFuncAttributeMaxDynamicSharedMemorySize, smem);

    k_rot    <<<(R_CNT + 255)/256, 256>>>(net, rotT, g_rot);
    k_misc   <<<4, 256>>>(zc, rv, out);
    k_hgather<<<(NGEO*BB*BB)/256, 256>>>(g_oper, out);
    k_erep   <<<(EREPN + 255)/256, 256>>>(net, g_rep, g_seg, out);
    k_geom   <<<NGEO, 256, smem>>>(S, G, rho, qn, mask, phiS, out);
}